// round 2
// baseline (speedup 1.0000x reference)
#include <cuda_runtime.h>

#define BB 2
#define TT 2048
#define CC 768
#define HH 12
#define NLEFT 6
#define DD 64
#define MM (BB*TT)
#define N1 (3*CC)

#define NEGF (-3.402823466e38f)

// Scratch (device globals: allocation-free)
__device__ float g_q[BB*HH*TT*DD];
__device__ float g_k[BB*HH*TT*DD];
__device__ float g_v[BB*HH*TT*DD];
__device__ float g_ctx[BB*TT*CC];

// ---------------------------------------------------------------------------
// GEMM 1: qkv = x @ Wqkv^T + b ; scatter to g_q/g_k/g_v in [B,H,T,D]
// C = A(MxK) * B(NxK)^T. BM=128, BN=64, BK=16, 256 threads, 8x4 per thread.
// ---------------------------------------------------------------------------
__global__ __launch_bounds__(256) void qkv_gemm_kernel(
    const float* __restrict__ x, const float* __restrict__ W,
    const float* __restrict__ bias)
{
    __shared__ float As[16 * 132];   // [k][m], stride 132 (16B-aligned rows)
    __shared__ float Bs[16 * 68];    // [k][n], stride 68

    const int K = CC;
    const int tid = threadIdx.x;
    const int m0 = blockIdx.y * 128;
    const int n0 = blockIdx.x * 64;
    const int tm = tid >> 4, tn = tid & 15;
    const int r0 = tm * 8, c0 = tn * 4;

    float acc[8][4];
#pragma unroll
    for (int i = 0; i < 8; i++)
#pragma unroll
        for (int j = 0; j < 4; j++) acc[i][j] = 0.f;

    for (int k0 = 0; k0 < K; k0 += 16) {
#pragma unroll
        for (int i = 0; i < 2; i++) {
            int lin = tid + i * 256;            // 512 float4 of A tile
            int row = lin >> 2, k4 = (lin & 3) << 2;
            float4 v = *(const float4*)(x + (size_t)(m0 + row) * K + k0 + k4);
            As[(k4 + 0) * 132 + row] = v.x;
            As[(k4 + 1) * 132 + row] = v.y;
            As[(k4 + 2) * 132 + row] = v.z;
            As[(k4 + 3) * 132 + row] = v.w;
        }
        {
            int row = tid >> 2, k4 = (tid & 3) << 2;  // 256 float4 of B tile
            float4 v = *(const float4*)(W + (size_t)(n0 + row) * K + k0 + k4);
            Bs[(k4 + 0) * 68 + row] = v.x;
            Bs[(k4 + 1) * 68 + row] = v.y;
            Bs[(k4 + 2) * 68 + row] = v.z;
            Bs[(k4 + 3) * 68 + row] = v.w;
        }
        __syncthreads();
#pragma unroll
        for (int kk = 0; kk < 16; kk++) {
            float4 a0 = *(const float4*)&As[kk * 132 + r0];
            float4 a1 = *(const float4*)&As[kk * 132 + r0 + 4];
            float4 bq = *(const float4*)&Bs[kk * 68 + c0];
            float ra[8] = {a0.x, a0.y, a0.z, a0.w, a1.x, a1.y, a1.z, a1.w};
            float rb[4] = {bq.x, bq.y, bq.z, bq.w};
#pragma unroll
            for (int i = 0; i < 8; i++)
#pragma unroll
                for (int j = 0; j < 4; j++)
                    acc[i][j] = fmaf(ra[i], rb[j], acc[i][j]);
        }
        __syncthreads();
    }

    // Epilogue: whole block maps to one (s, h) since 64 | 768 and 64 == D.
    const int s  = n0 / CC;
    const int hh = (n0 % CC) / DD;
    float* dst = (s == 0) ? g_q : ((s == 1) ? g_k : g_v);
    float4 bv = *(const float4*)(bias + n0 + c0);

#pragma unroll
    for (int i = 0; i < 8; i++) {
        int m = m0 + r0 + i;
        int b = m / TT, t = m % TT;
        float4 o;
        o.x = acc[i][0] + bv.x;
        o.y = acc[i][1] + bv.y;
        o.z = acc[i][2] + bv.z;
        o.w = acc[i][3] + bv.w;
        *(float4*)(dst + ((size_t)(b * HH + hh) * TT + t) * DD + c0) = o;
    }
}

// ---------------------------------------------------------------------------
// Flash attention: one CTA per (b*h, 64-row q block). 256 threads.
// Left heads (h < NLEFT): causal (k <= q). Right heads: anti-causal (k >= q).
// Row softmax stats live in registers, reduced via 16-lane shuffles.
// Smem: Qst[64][68] (Q^T), KPst[64][68] (K^T, reused for P^T), Vs[64][64].
// ---------------------------------------------------------------------------
__global__ __launch_bounds__(256) void attn_kernel(const int* __restrict__ amask)
{
    extern __shared__ float sm[];
    float* Qst  = sm;                  // 64*68
    float* KPst = sm + 64 * 68;        // 64*68
    float* Vs   = sm + 2 * 64 * 68;    // 64*64

    const int bh = blockIdx.x;         // 0..23
    const int qb = blockIdx.y;         // 0..31
    const int b = bh / HH;
    const int h = bh % HH;
    const bool left = (h < NLEFT);

    const float* Qg = g_q + (size_t)bh * TT * DD;
    const float* Kg = g_k + (size_t)bh * TT * DD;
    const float* Vg = g_v + (size_t)bh * TT * DD;

    const int tid = threadIdx.x;
    const int tm = tid >> 4, tn = tid & 15;
    const int r0 = tm * 4, c0 = tn * 4;

    // Load Q tile transposed: Qst[d][r]
#pragma unroll
    for (int i = 0; i < 4; i++) {
        int lin = tid + i * 256;       // 1024 float4
        int row = lin >> 4, d4 = (lin & 15) << 2;
        float4 v = *(const float4*)(Qg + (size_t)(qb * 64 + row) * DD + d4);
        Qst[(d4 + 0) * 68 + row] = v.x;
        Qst[(d4 + 1) * 68 + row] = v.y;
        Qst[(d4 + 2) * 68 + row] = v.z;
        Qst[(d4 + 3) * 68 + row] = v.w;
    }

    float m_r[4] = {NEGF, NEGF, NEGF, NEGF};
    float l_r[4] = {0.f, 0.f, 0.f, 0.f};
    float O[4][4];
#pragma unroll
    for (int i = 0; i < 4; i++)
#pragma unroll
        for (int j = 0; j < 4; j++) O[i][j] = 0.f;

    const int kb0 = left ? 0 : qb;
    const int kb1 = left ? qb : (TT / 64 - 1);

    for (int kb = kb0; kb <= kb1; kb++) {
        __syncthreads();   // previous PV/loads done before overwriting tiles
#pragma unroll
        for (int i = 0; i < 4; i++) {
            int lin = tid + i * 256;
            int row = lin >> 4, d4 = (lin & 15) << 2;
            float4 kv = *(const float4*)(Kg + (size_t)(kb * 64 + row) * DD + d4);
            KPst[(d4 + 0) * 68 + row] = kv.x;
            KPst[(d4 + 1) * 68 + row] = kv.y;
            KPst[(d4 + 2) * 68 + row] = kv.z;
            KPst[(d4 + 3) * 68 + row] = kv.w;
            float4 vv = *(const float4*)(Vg + (size_t)(kb * 64 + row) * DD + d4);
            *(float4*)(Vs + row * 64 + d4) = vv;
        }
        __syncthreads();

        // S = Q @ K^T  (4x4 per thread)
        float S[4][4];
#pragma unroll
        for (int i = 0; i < 4; i++)
#pragma unroll
            for (int j = 0; j < 4; j++) S[i][j] = 0.f;

#pragma unroll 8
        for (int d = 0; d < 64; d++) {
            float4 q4 = *(const float4*)&Qst[d * 68 + r0];
            float4 k4 = *(const float4*)&KPst[d * 68 + c0];
            float qa[4] = {q4.x, q4.y, q4.z, q4.w};
            float ka[4] = {k4.x, k4.y, k4.z, k4.w};
#pragma unroll
            for (int i = 0; i < 4; i++)
#pragma unroll
                for (int j = 0; j < 4; j++)
                    S[i][j] = fmaf(qa[i], ka[j], S[i][j]);
        }

        // Mask + online softmax update
        const int kbase = kb * 64;
        float pen[4];
#pragma unroll
        for (int j = 0; j < 4; j++) {
            int ki = kbase + c0 + j;
            pen[j] = amask[b * TT + ki] ? 0.f : NEGF;
        }

        float mx[4];
#pragma unroll
        for (int i = 0; i < 4; i++) {
            int qi = qb * 64 + r0 + i;
            float mm = NEGF;
#pragma unroll
            for (int j = 0; j < 4; j++) {
                int ki = kbase + c0 + j;
                bool valid = left ? (ki <= qi) : (ki >= qi);
                float sv = S[i][j] * 0.125f + (valid ? 0.f : NEGF) + pen[j];
                S[i][j] = sv;
                mm = fmaxf(mm, sv);
            }
            mx[i] = mm;
        }
#pragma unroll
        for (int off = 8; off >= 1; off >>= 1)
#pragma unroll
            for (int i = 0; i < 4; i++)
                mx[i] = fmaxf(mx[i], __shfl_xor_sync(0xffffffffu, mx[i], off));

        float alpha[4], rs[4];
#pragma unroll
        for (int i = 0; i < 4; i++) {
            float mn = fmaxf(m_r[i], mx[i]);
            alpha[i] = __expf(m_r[i] - mn);
            m_r[i] = mn;
            float s0 = 0.f;
#pragma unroll
            for (int j = 0; j < 4; j++) {
                float p = __expf(S[i][j] - mn);
                S[i][j] = p;
                s0 += p;
            }
            rs[i] = s0;
        }
#pragma unroll
        for (int off = 8; off >= 1; off >>= 1)
#pragma unroll
            for (int i = 0; i < 4; i++)
                rs[i] += __shfl_xor_sync(0xffffffffu, rs[i], off);
#pragma unroll
        for (int i = 0; i < 4; i++) {
            l_r[i] = l_r[i] * alpha[i] + rs[i];
#pragma unroll
            for (int j = 0; j < 4; j++) O[i][j] *= alpha[i];
        }

        __syncthreads();   // everyone done reading K^T before P^T overwrite
#pragma unroll
        for (int j = 0; j < 4; j++) {
            float4 pv = make_float4(S[0][j], S[1][j], S[2][j], S[3][j]);
            *(float4*)&KPst[(c0 + j) * 68 + r0] = pv;
        }
        __syncthreads();

        // O += P @ V
#pragma unroll 8
        for (int j2 = 0; j2 < 64; j2++) {
            float4 p4 = *(const float4*)&KPst[j2 * 68 + r0];
            float4 v4 = *(const float4*)&Vs[j2 * 64 + c0];
            float pa[4] = {p4.x, p4.y, p4.z, p4.w};
            float va[4] = {v4.x, v4.y, v4.z, v4.w};
#pragma unroll
            for (int i = 0; i < 4; i++)
#pragma unroll
                for (int j = 0; j < 4; j++)
                    O[i][j] = fmaf(pa[i], va[j], O[i][j]);
        }
    }

    // Normalize + write ctx [B, T, C] at column h*D
#pragma unroll
    for (int i = 0; i < 4; i++) {
        float inv = 1.0f / l_r[i];
        int t = qb * 64 + r0 + i;
        float4 o = make_float4(O[i][0] * inv, O[i][1] * inv,
                               O[i][2] * inv, O[i][3] * inv);
        *(float4*)(g_ctx + ((size_t)b * TT + t) * CC + h * DD + c0) = o;
    }
}

// ---------------------------------------------------------------------------
// GEMM 2: out = ctx @ Wo^T + b. Same NT tiling as GEMM 1.
// ---------------------------------------------------------------------------
__global__ __launch_bounds__(256) void out_gemm_kernel(
    const float* __restrict__ W, const float* __restrict__ bias,
    float* __restrict__ out)
{
    __shared__ float As[16 * 132];
    __shared__ float Bs[16 * 68];

    const int K = CC;
    const int tid = threadIdx.x;
    const int m0 = blockIdx.y * 128;
    const int n0 = blockIdx.x * 64;
    const int tm = tid >> 4, tn = tid & 15;
    const int r0 = tm * 8, c0 = tn * 4;

    float acc[8][4];
#pragma unroll
    for (int i = 0; i < 8; i++)
#pragma unroll
        for (int j = 0; j < 4; j++) acc[i][j] = 0.f;

    for (int k0 = 0; k0 < K; k0 += 16) {
#pragma unroll
        for (int i = 0; i < 2; i++) {
            int lin = tid + i * 256;
            int row = lin >> 2, k4 = (lin & 3) << 2;
            float4 v = *(const float4*)(g_ctx + (size_t)(m0 + row) * K + k0 + k4);
            As[(k4 + 0) * 132 + row] = v.x;
            As[(k4 + 1) * 132 + row] = v.y;
            As[(k4 + 2) * 132 + row] = v.z;
            As[(k4 + 3) * 132 + row] = v.w;
        }
        {
            int row = tid >> 2, k4 = (tid & 3) << 2;
            float4 v = *(const float4*)(W + (size_t)(n0 + row) * K + k0 + k4);
            Bs[(k4 + 0) * 68 + row] = v.x;
            Bs[(k4 + 1) * 68 + row] = v.y;
            Bs[(k4 + 2) * 68 + row] = v.z;
            Bs[(k4 + 3) * 68 + row] = v.w;
        }
        __syncthreads();
#pragma unroll
        for (int kk = 0; kk < 16; kk++) {
            float4 a0 = *(const float4*)&As[kk * 132 + r0];
            float4 a1 = *(const float4*)&As[kk * 132 + r0 + 4];
            float4 bq = *(const float4*)&Bs[kk * 68 + c0];
            float ra[8] = {a0.x, a0.y, a0.z, a0.w, a1.x, a1.y, a1.z, a1.w};
            float rb[4] = {bq.x, bq.y, bq.z, bq.w};
#pragma unroll
            for (int i = 0; i < 8; i++)
#pragma unroll
                for (int j = 0; j < 4; j++)
                    acc[i][j] = fmaf(ra[i], rb[j], acc[i][j]);
        }
        __syncthreads();
    }

    float4 bv = *(const float4*)(bias + n0 + c0);
#pragma unroll
    for (int i = 0; i < 8; i++) {
        int m = m0 + r0 + i;
        float4 o;
        o.x = acc[i][0] + bv.x;
        o.y = acc[i][1] + bv.y;
        o.z = acc[i][2] + bv.z;
        o.w = acc[i][3] + bv.w;
        *(float4*)(out + (size_t)m * CC + n0 + c0) = o;
    }
}

// ---------------------------------------------------------------------------
extern "C" void kernel_launch(void* const* d_in, const int* in_sizes, int n_in,
                              void* d_out, int out_size)
{
    const float* x      = (const float*)d_in[0];
    const int*   amask  = (const int*)  d_in[1];
    const float* Wqkv_w = (const float*)d_in[2];
    const float* Wqkv_b = (const float*)d_in[3];
    const float* Wo_w   = (const float*)d_in[4];
    const float* Wo_b   = (const float*)d_in[5];
    float* out = (float*)d_out;

    (void)in_sizes; (void)n_in; (void)out_size;

    const int attn_smem = (2 * 64 * 68 + 64 * 64) * 4;  // 51200 bytes
    cudaFuncSetAttribute(attn_kernel,
                         cudaFuncAttributeMaxDynamicSharedMemorySize, attn_smem);

    qkv_gemm_kernel<<<dim3(N1 / 64, MM / 128), 256>>>(x, Wqkv_w, Wqkv_b);
    attn_kernel<<<dim3(BB * HH, TT / 64), 256, attn_smem>>>(amask);
    out_gemm_kernel<<<dim3(CC / 64, MM / 128), 256>>>(Wo_w, Wo_b, out);
}

// round 3
// speedup vs baseline: 2.7501x; 2.7501x over previous
#include <cuda_runtime.h>

#define BB 2
#define TT 2048
#define CC 768
#define HH 12
#define NLEFT 6
#define DD 64
#define MM (BB*TT)
#define N1 (3*CC)

#define NEGF (-3.402823466e38f)

// Scratch (device globals: allocation-free)
__device__ float g_q[BB*HH*TT*DD];
__device__ float g_k[BB*HH*TT*DD];
__device__ float g_v[BB*HH*TT*DD];
__device__ float g_ctx[BB*TT*CC];

__device__ __forceinline__ unsigned f2tf32(float f) {
    unsigned r;
    asm("cvt.rna.tf32.f32 %0, %1;" : "=r"(r) : "f"(f));
    return r;
}

// D += A(16x8,row) * B(8x8,col)  tf32 -> f32
__device__ __forceinline__ void mma8(float* d,
    unsigned a0, unsigned a1, unsigned a2, unsigned a3,
    unsigned b0, unsigned b1)
{
    asm volatile(
        "mma.sync.aligned.m16n8k8.row.col.f32.tf32.tf32.f32 "
        "{%0,%1,%2,%3}, {%4,%5,%6,%7}, {%8,%9}, {%0,%1,%2,%3};"
        : "+f"(d[0]), "+f"(d[1]), "+f"(d[2]), "+f"(d[3])
        : "r"(a0), "r"(a1), "r"(a2), "r"(a3), "r"(b0), "r"(b1));
}

// ---------------------------------------------------------------------------
// tf32 MMA GEMM: C = A(MxK) @ W(NxK)^T + bias.
// BM=128, BN=64, BK=32. 256 thr = 8 warps (4M x 2N), warp tile 32x32.
// MODE 0: A = x, scatter to g_q/g_k/g_v.  MODE 1: A = g_ctx, write out.
// ---------------------------------------------------------------------------
template<int MODE>
__global__ __launch_bounds__(256) void mma_gemm_kernel(
    const float* __restrict__ A_in, const float* __restrict__ W,
    const float* __restrict__ bias, float* __restrict__ out)
{
    __shared__ unsigned As[128 * 36];   // [m][k], pad 36 -> conflict-free frags
    __shared__ unsigned Bs[64 * 36];    // [n][k]

    const float* Ag = (MODE == 0) ? A_in : (const float*)g_ctx;

    const int K = CC;
    const int tid  = threadIdx.x;
    const int lane = tid & 31, warp = tid >> 5;
    const int mw = warp >> 1, nw = warp & 1;
    const int m0 = blockIdx.y * 128, n0 = blockIdx.x * 64;
    const int g = lane >> 2, t = lane & 3;

    float acc[2][4][4];
#pragma unroll
    for (int mt = 0; mt < 2; mt++)
#pragma unroll
        for (int nt = 0; nt < 4; nt++)
#pragma unroll
            for (int c = 0; c < 4; c++) acc[mt][nt][c] = 0.f;

    for (int k0 = 0; k0 < K; k0 += 32) {
#pragma unroll
        for (int i = 0; i < 4; i++) {          // 1024 float4 of A
            int idx = tid + i * 256;
            int row = idx >> 3, kq = (idx & 7) << 2;
            float4 v = *(const float4*)(Ag + (size_t)(m0 + row) * K + k0 + kq);
            As[row * 36 + kq + 0] = f2tf32(v.x);
            As[row * 36 + kq + 1] = f2tf32(v.y);
            As[row * 36 + kq + 2] = f2tf32(v.z);
            As[row * 36 + kq + 3] = f2tf32(v.w);
        }
#pragma unroll
        for (int i = 0; i < 2; i++) {          // 512 float4 of B
            int idx = tid + i * 256;
            int row = idx >> 3, kq = (idx & 7) << 2;
            float4 v = *(const float4*)(W + (size_t)(n0 + row) * K + k0 + kq);
            Bs[row * 36 + kq + 0] = f2tf32(v.x);
            Bs[row * 36 + kq + 1] = f2tf32(v.y);
            Bs[row * 36 + kq + 2] = f2tf32(v.z);
            Bs[row * 36 + kq + 3] = f2tf32(v.w);
        }
        __syncthreads();

#pragma unroll
        for (int ks = 0; ks < 4; ks++) {
            const int kk = ks * 8;
            unsigned af[2][4], bf[4][2];
#pragma unroll
            for (int mt = 0; mt < 2; mt++) {
                int rm = mw * 32 + mt * 16;
                af[mt][0] = As[(rm     + g) * 36 + kk     + t];
                af[mt][1] = As[(rm + 8 + g) * 36 + kk     + t];
                af[mt][2] = As[(rm     + g) * 36 + kk + 4 + t];
                af[mt][3] = As[(rm + 8 + g) * 36 + kk + 4 + t];
            }
#pragma unroll
            for (int nt = 0; nt < 4; nt++) {
                int rn = nw * 32 + nt * 8;
                bf[nt][0] = Bs[(rn + g) * 36 + kk     + t];
                bf[nt][1] = Bs[(rn + g) * 36 + kk + 4 + t];
            }
#pragma unroll
            for (int mt = 0; mt < 2; mt++)
#pragma unroll
                for (int nt = 0; nt < 4; nt++)
                    mma8(acc[mt][nt], af[mt][0], af[mt][1], af[mt][2], af[mt][3],
                         bf[nt][0], bf[nt][1]);
        }
        __syncthreads();
    }

    // Epilogue. C frag: rows g, g+8 ; cols t*2, t*2+1.
    if (MODE == 0) {
        const int s  = n0 / CC;
        const int hh = (n0 % CC) / DD;
        float* dst = (s == 0) ? g_q : ((s == 1) ? g_k : g_v);
#pragma unroll
        for (int mt = 0; mt < 2; mt++) {
            int m = m0 + mw * 32 + mt * 16 + g;
            int b0i = m >> 11, tok0 = m & 2047;
            int m1 = m + 8, b1i = m1 >> 11, tok1 = m1 & 2047;
#pragma unroll
            for (int nt = 0; nt < 4; nt++) {
                int dcol = nw * 32 + nt * 8 + t * 2;
                int n = n0 + dcol;
                float bv0 = bias[n], bv1 = bias[n + 1];
                float2 r0 = make_float2(acc[mt][nt][0] + bv0, acc[mt][nt][1] + bv1);
                float2 r1 = make_float2(acc[mt][nt][2] + bv0, acc[mt][nt][3] + bv1);
                *(float2*)(dst + ((size_t)(b0i * HH + hh) * TT + tok0) * DD + dcol) = r0;
                *(float2*)(dst + ((size_t)(b1i * HH + hh) * TT + tok1) * DD + dcol) = r1;
            }
        }
    } else {
#pragma unroll
        for (int mt = 0; mt < 2; mt++) {
            int m = m0 + mw * 32 + mt * 16 + g;
#pragma unroll
            for (int nt = 0; nt < 4; nt++) {
                int n = n0 + nw * 32 + nt * 8 + t * 2;
                float bv0 = bias[n], bv1 = bias[n + 1];
                float2 r0 = make_float2(acc[mt][nt][0] + bv0, acc[mt][nt][1] + bv1);
                float2 r1 = make_float2(acc[mt][nt][2] + bv0, acc[mt][nt][3] + bv1);
                *(float2*)(out + (size_t)m * CC + n) = r0;
                *(float2*)(out + (size_t)(m + 8) * CC + n) = r1;
            }
        }
    }
}

// ---------------------------------------------------------------------------
// tf32 MMA flash attention. 128 thr = 4 warps; warp owns 16 q-rows x 64 k-cols
// so softmax row stats need only intra-quad shuffles. Q pre-scaled by 1/8.
// Causal mask applied only on the diagonal k-block.
// smem (dynamic): Qs,Ks,Vs,Ps [64][68] tf32 + pm[64] f32.
// ---------------------------------------------------------------------------
__global__ __launch_bounds__(128) void attn_mma_kernel(const int* __restrict__ amask)
{
    extern __shared__ unsigned smu[];
    unsigned* Qs = smu;                 // [q][d]
    unsigned* Ks = smu + 64 * 68;       // [kcol][d]
    unsigned* Vs = smu + 2 * 64 * 68;   // [kseq][d]
    unsigned* Ps = smu + 3 * 64 * 68;   // [q][kseq]  (warp-private rows)
    float*    pm = (float*)(smu + 4 * 64 * 68);

    const int bh = blockIdx.x, qb = blockIdx.y;
    const int b = bh / HH, h = bh % HH;
    const bool left = (h < NLEFT);

    const float* Qg = g_q + (size_t)bh * TT * DD;
    const float* Kg = g_k + (size_t)bh * TT * DD;
    const float* Vg = g_v + (size_t)bh * TT * DD;

    const int tid = threadIdx.x;
    const int lane = tid & 31, warp = tid >> 5;
    const int g = lane >> 2, t = lane & 3;
    const int rm = warp * 16;

    // Load Q (scaled by 1/8, exact)
#pragma unroll
    for (int i = 0; i < 8; i++) {
        int idx = tid + i * 128;
        int row = idx >> 4, d4 = (idx & 15) << 2;
        float4 v = *(const float4*)(Qg + (size_t)(qb * 64 + row) * DD + d4);
        Qs[row * 68 + d4 + 0] = f2tf32(v.x * 0.125f);
        Qs[row * 68 + d4 + 1] = f2tf32(v.y * 0.125f);
        Qs[row * 68 + d4 + 2] = f2tf32(v.z * 0.125f);
        Qs[row * 68 + d4 + 3] = f2tf32(v.w * 0.125f);
    }

    float m_r[2] = {NEGF, NEGF};
    float l_r[2] = {0.f, 0.f};
    float O[8][4];
#pragma unroll
    for (int nt = 0; nt < 8; nt++)
#pragma unroll
        for (int c = 0; c < 4; c++) O[nt][c] = 0.f;

    const int kb0 = left ? 0 : qb;
    const int kb1 = left ? qb : (TT / 64 - 1);
    const int qi0 = qb * 64 + rm + g, qi1 = qi0 + 8;

    for (int kb = kb0; kb <= kb1; kb++) {
        __syncthreads();                       // prev iter done with Ks/Vs
#pragma unroll
        for (int i = 0; i < 8; i++) {
            int idx = tid + i * 128;
            int row = idx >> 4, d4 = (idx & 15) << 2;
            float4 kv = *(const float4*)(Kg + (size_t)(kb * 64 + row) * DD + d4);
            Ks[row * 68 + d4 + 0] = f2tf32(kv.x);
            Ks[row * 68 + d4 + 1] = f2tf32(kv.y);
            Ks[row * 68 + d4 + 2] = f2tf32(kv.z);
            Ks[row * 68 + d4 + 3] = f2tf32(kv.w);
            float4 vv = *(const float4*)(Vg + (size_t)(kb * 64 + row) * DD + d4);
            Vs[row * 68 + d4 + 0] = f2tf32(vv.x);
            Vs[row * 68 + d4 + 1] = f2tf32(vv.y);
            Vs[row * 68 + d4 + 2] = f2tf32(vv.z);
            Vs[row * 68 + d4 + 3] = f2tf32(vv.w);
        }
        if (tid < 64)
            pm[tid] = amask[b * TT + kb * 64 + tid] ? 0.f : NEGF;
        __syncthreads();

        // S = Qs @ Ks^T  (warp: 16 rows x 64 cols)
        float S[8][4];
#pragma unroll
        for (int nt = 0; nt < 8; nt++)
#pragma unroll
            for (int c = 0; c < 4; c++) S[nt][c] = 0.f;

#pragma unroll
        for (int ks = 0; ks < 8; ks++) {
            const int kk = ks * 8;
            unsigned a0 = Qs[(rm     + g) * 68 + kk     + t];
            unsigned a1 = Qs[(rm + 8 + g) * 68 + kk     + t];
            unsigned a2 = Qs[(rm     + g) * 68 + kk + 4 + t];
            unsigned a3 = Qs[(rm + 8 + g) * 68 + kk + 4 + t];
#pragma unroll
            for (int nt = 0; nt < 8; nt++) {
                unsigned b0 = Ks[(nt * 8 + g) * 68 + kk     + t];
                unsigned b1 = Ks[(nt * 8 + g) * 68 + kk + 4 + t];
                mma8(S[nt], a0, a1, a2, a3, b0, b1);
            }
        }

        // Mask + online softmax (C frag cols = t*2, t*2+1; rows g, g+8)
        float mx0 = NEGF, mx1 = NEGF;
        const bool diag = (kb == qb);
#pragma unroll
        for (int nt = 0; nt < 8; nt++) {
            int c0 = nt * 8 + t * 2;
            float p0 = pm[c0], p1 = pm[c0 + 1];
            float s0 = S[nt][0] + p0, s1 = S[nt][1] + p1;
            float s2 = S[nt][2] + p0, s3 = S[nt][3] + p1;
            if (diag) {
                int k0i = kb * 64 + c0, k1i = k0i + 1;
                if (left) {
                    if (k0i > qi0) s0 = NEGF;
                    if (k1i > qi0) s1 = NEGF;
                    if (k0i > qi1) s2 = NEGF;
                    if (k1i > qi1) s3 = NEGF;
                } else {
                    if (k0i < qi0) s0 = NEGF;
                    if (k1i < qi0) s1 = NEGF;
                    if (k0i < qi1) s2 = NEGF;
                    if (k1i < qi1) s3 = NEGF;
                }
            }
            S[nt][0] = s0; S[nt][1] = s1; S[nt][2] = s2; S[nt][3] = s3;
            mx0 = fmaxf(mx0, fmaxf(s0, s1));
            mx1 = fmaxf(mx1, fmaxf(s2, s3));
        }
        mx0 = fmaxf(mx0, __shfl_xor_sync(0xffffffffu, mx0, 1));
        mx0 = fmaxf(mx0, __shfl_xor_sync(0xffffffffu, mx0, 2));
        mx1 = fmaxf(mx1, __shfl_xor_sync(0xffffffffu, mx1, 1));
        mx1 = fmaxf(mx1, __shfl_xor_sync(0xffffffffu, mx1, 2));

        float mn0 = fmaxf(m_r[0], mx0), mn1 = fmaxf(m_r[1], mx1);
        float al0 = __expf(m_r[0] - mn0), al1 = __expf(m_r[1] - mn1);
        m_r[0] = mn0; m_r[1] = mn1;

        float rs0 = 0.f, rs1 = 0.f;
#pragma unroll
        for (int nt = 0; nt < 8; nt++) {
            float e0 = __expf(S[nt][0] - mn0), e1 = __expf(S[nt][1] - mn0);
            float e2 = __expf(S[nt][2] - mn1), e3 = __expf(S[nt][3] - mn1);
            S[nt][0] = e0; S[nt][1] = e1; S[nt][2] = e2; S[nt][3] = e3;
            rs0 += e0 + e1; rs1 += e2 + e3;
        }
        rs0 += __shfl_xor_sync(0xffffffffu, rs0, 1);
        rs0 += __shfl_xor_sync(0xffffffffu, rs0, 2);
        rs1 += __shfl_xor_sync(0xffffffffu, rs1, 1);
        rs1 += __shfl_xor_sync(0xffffffffu, rs1, 2);
        l_r[0] = l_r[0] * al0 + rs0;
        l_r[1] = l_r[1] * al1 + rs1;
#pragma unroll
        for (int nt = 0; nt < 8; nt++) {
            O[nt][0] *= al0; O[nt][1] *= al0;
            O[nt][2] *= al1; O[nt][3] *= al1;
        }

        // P -> smem (tf32, warp-private rows)
        __syncwarp();
#pragma unroll
        for (int nt = 0; nt < 8; nt++) {
            int c0 = nt * 8 + t * 2;
            Ps[(rm     + g) * 68 + c0    ] = f2tf32(S[nt][0]);
            Ps[(rm     + g) * 68 + c0 + 1] = f2tf32(S[nt][1]);
            Ps[(rm + 8 + g) * 68 + c0    ] = f2tf32(S[nt][2]);
            Ps[(rm + 8 + g) * 68 + c0 + 1] = f2tf32(S[nt][3]);
        }
        __syncwarp();

        // O += P @ V
#pragma unroll
        for (int ks = 0; ks < 8; ks++) {
            const int kk = ks * 8;
            unsigned a0 = Ps[(rm     + g) * 68 + kk     + t];
            unsigned a1 = Ps[(rm + 8 + g) * 68 + kk     + t];
            unsigned a2 = Ps[(rm     + g) * 68 + kk + 4 + t];
            unsigned a3 = Ps[(rm + 8 + g) * 68 + kk + 4 + t];
#pragma unroll
            for (int nt = 0; nt < 8; nt++) {
                unsigned b0 = Vs[(kk     + t) * 68 + nt * 8 + g];
                unsigned b1 = Vs[(kk + 4 + t) * 68 + nt * 8 + g];
                mma8(O[nt], a0, a1, a2, a3, b0, b1);
            }
        }
    }

    // Epilogue -> g_ctx
    float inv0 = 1.0f / l_r[0], inv1 = 1.0f / l_r[1];
    int t0 = qb * 64 + rm + g, t1 = t0 + 8;
#pragma unroll
    for (int nt = 0; nt < 8; nt++) {
        int col = h * DD + nt * 8 + t * 2;
        *(float2*)(g_ctx + ((size_t)b * TT + t0) * CC + col) =
            make_float2(O[nt][0] * inv0, O[nt][1] * inv0);
        *(float2*)(g_ctx + ((size_t)b * TT + t1) * CC + col) =
            make_float2(O[nt][2] * inv1, O[nt][3] * inv1);
    }
}

// ---------------------------------------------------------------------------
extern "C" void kernel_launch(void* const* d_in, const int* in_sizes, int n_in,
                              void* d_out, int out_size)
{
    const float* x      = (const float*)d_in[0];
    const int*   amask  = (const int*)  d_in[1];
    const float* Wqkv_w = (const float*)d_in[2];
    const float* Wqkv_b = (const float*)d_in[3];
    const float* Wo_w   = (const float*)d_in[4];
    const float* Wo_b   = (const float*)d_in[5];
    float* out = (float*)d_out;

    (void)in_sizes; (void)n_in; (void)out_size;

    const int attn_smem = 4 * 64 * 68 * 4 + 64 * 4;   // 69888 B
    cudaFuncSetAttribute(attn_mma_kernel,
                         cudaFuncAttributeMaxDynamicSharedMemorySize, attn_smem);

    mma_gemm_kernel<0><<<dim3(N1 / 64, MM / 128), 256>>>(x, Wqkv_w, Wqkv_b, nullptr);
    attn_mma_kernel<<<dim3(BB * HH, TT / 64), 128, attn_smem>>>(amask);
    mma_gemm_kernel<1><<<dim3(CC / 64, MM / 128), 256>>>(nullptr, Wo_w, Wo_b, out);
}